// round 1
// baseline (speedup 1.0000x reference)
#include <cuda_runtime.h>

#define FULL_MASK 0xffffffffu

// sigmoid(x) = 1/(1+exp(-x)) : 2 MUFU (EX2, RCP) + 2 FMA-class ops
__device__ __forceinline__ float fsigmoid(float x) {
    return __fdividef(1.0f, 1.0f + __expf(-x));
}

// One warp per row of 1024 floats. Lane t owns contiguous leaves [32t, 32t+32).
// Complete binary tree, depth 10:
//   levels d=5..9 : entirely within-lane (31 sigmoids, vectorized over lanes)
//   levels d=0..4 : cross-lane via shfl_xor butterfly (5 sigmoids)
// class_prob[leaf] = product of the 10 per-level child probabilities.
__global__ void __launch_bounds__(256, 2)
nbdt_kernel(const float* __restrict__ in, float* __restrict__ out)
{
    __shared__ float4 sm[8 * 256];   // 4 KB per warp, 32 KB per block
    const int warp = threadIdx.x >> 5;
    const int lane = threadIdx.x & 31;
    const int row  = (blockIdx.x << 3) + warp;

    float4* buf = sm + warp * 256;

    // ---- coalesced global load -> swizzled SMEM ----
    const float4* rin = reinterpret_cast<const float4*>(in) + (size_t)row * 256;
    #pragma unroll
    for (int k = 0; k < 8; k++) {
        int L = lane + (k << 5);               // logical float4 index in row
        buf[L ^ ((L >> 3) & 7)] = rin[L];      // conflict-free swizzled store
    }
    __syncwarp();

    // ---- contiguous per-lane read (conflict-free) + deepest-level prep ----
    // s2[i] = v[2i]+v[2i+1]  (sums of leaf pairs), d9[i] = v[2i]-v[2i+1]
    float s2[16], d9[16];
    #pragma unroll
    for (int j = 0; j < 8; j++) {
        int L = (lane << 3) + j;               // logical float4: leaves [32*lane+4j, +4)
        float4 t = buf[L ^ ((L >> 3) & 7)];
        s2[2*j]   = t.x + t.y;  d9[2*j]   = t.x - t.y;
        s2[2*j+1] = t.z + t.w;  d9[2*j+1] = t.z - t.w;
    }

    // ---- within-lane sum tree ----
    float s4[8], s8[4], s16[2];
    #pragma unroll
    for (int i = 0; i < 8; i++) s4[i] = s2[2*i] + s2[2*i+1];
    #pragma unroll
    for (int i = 0; i < 4; i++) s8[i] = s4[2*i] + s4[2*i+1];
    s16[0] = s8[0] + s8[1];
    s16[1] = s8[2] + s8[3];
    float sum = s16[0] + s16[1];               // sum of my 32 leaves

    // ---- cross-lane levels d=4..0 (butterfly) ----
    // At step s: my group = 2^s lanes (32*2^s leaves); sibling via xor(1<<s).
    // My child's softmax prob = sigmoid(my_mean - sibling_mean), side-independent.
    float acc = 1.0f;
    float inv = 1.0f / 32.0f;
    #pragma unroll
    for (int s = 0; s < 5; s++) {
        float part = __shfl_xor_sync(FULL_MASK, sum, 1 << s);
        acc *= fsigmoid((sum - part) * inv);
        sum += part;
        inv *= 0.5f;
    }

    // ---- within-lane top-down: levels d=5..8 ----
    float p16[2];
    {
        float pl = fsigmoid((s16[0] - s16[1]) * (1.0f / 16.0f));
        float a = acc * pl;  p16[0] = a;  p16[1] = acc - a;
    }
    float p8[4];
    #pragma unroll
    for (int i = 0; i < 2; i++) {
        float pl = fsigmoid((s8[2*i] - s8[2*i+1]) * 0.125f);
        float a = p16[i] * pl;  p8[2*i] = a;  p8[2*i+1] = p16[i] - a;
    }
    float p4[8];
    #pragma unroll
    for (int i = 0; i < 4; i++) {
        float pl = fsigmoid((s4[2*i] - s4[2*i+1]) * 0.25f);
        float a = p8[i] * pl;  p4[2*i] = a;  p4[2*i+1] = p8[i] - a;
    }
    float p2[16];
    #pragma unroll
    for (int i = 0; i < 8; i++) {
        float pl = fsigmoid((s2[2*i] - s2[2*i+1]) * 0.5f);
        float a = p4[i] * pl;  p2[2*i] = a;  p2[2*i+1] = p4[i] - a;
    }

    __syncwarp();   // everyone done reading input tile before overwriting buf

    // ---- level d=9 (leaf pairs) + swizzled SMEM store ----
    #pragma unroll
    for (int j = 0; j < 8; j++) {
        float pl0 = fsigmoid(d9[2*j]);
        float a0 = p2[2*j] * pl0,   b0 = p2[2*j]   - a0;
        float pl1 = fsigmoid(d9[2*j+1]);
        float a1 = p2[2*j+1] * pl1, b1 = p2[2*j+1] - a1;
        int L = (lane << 3) + j;
        buf[L ^ ((L >> 3) & 7)] = make_float4(a0, b0, a1, b1);
    }
    __syncwarp();

    // ---- SMEM -> coalesced global store ----
    float4* rout = reinterpret_cast<float4*>(out) + (size_t)row * 256;
    #pragma unroll
    for (int k = 0; k < 8; k++) {
        int L = lane + (k << 5);
        rout[L] = buf[L ^ ((L >> 3) & 7)];
    }
}

extern "C" void kernel_launch(void* const* d_in, const int* in_sizes, int n_in,
                              void* d_out, int out_size)
{
    const float* in = (const float*)d_in[0];
    float* out = (float*)d_out;
    int rows = in_sizes[0] / 1024;             // BATCH = 16384
    nbdt_kernel<<<rows / 8, 256>>>(in, out);
}

// round 2
// speedup vs baseline: 1.1403x; 1.1403x over previous
#include <cuda_runtime.h>

#define FULL_MASK 0xffffffffu

// sigmoid(x) = 1/(1+exp(-x)) : softmax over 2 children collapses to this
__device__ __forceinline__ float fsigmoid(float x) {
    return __fdividef(1.0f, 1.0f + __expf(-x));
}

// One warp per row of 1024 floats. Lane t owns contiguous leaves [32t, 32t+32).
// Complete binary tree, depth 10:
//   levels d=5..9 : entirely within-lane (vectorized across lanes)
//   levels d=0..4 : cross-lane via shfl_xor butterfly (5 sigmoids)
// class_prob[leaf] = product of per-level child probabilities along its path.
// SMEM staging (XOR-swizzled in float4 units) converts between coalesced
// global access and contiguous-per-lane access, conflict-free both ways.
__global__ void __launch_bounds__(256, 4)
nbdt_kernel(const float* __restrict__ in, float* __restrict__ out)
{
    __shared__ float4 sm[8 * 256];   // 4 KB per warp, 32 KB per block
    const int warp = threadIdx.x >> 5;
    const int lane = threadIdx.x & 31;
    const int row  = (blockIdx.x << 3) + warp;

    float4* buf = sm + warp * 256;

    // ---- coalesced global load -> swizzled SMEM ----
    const float4* rin = reinterpret_cast<const float4*>(in) + (size_t)row * 256;
    #pragma unroll
    for (int k = 0; k < 8; k++) {
        int L = lane + (k << 5);               // logical float4 index in row
        buf[L ^ ((L >> 3) & 7)] = rin[L];      // conflict-free swizzled store
    }
    __syncwarp();

    // ---- contiguous per-lane read (conflict-free): pair sums only ----
    // s2[i] = v[2i]+v[2i+1]; leaf-level diffs recomputed later from SMEM.
    float s2[16];
    #pragma unroll
    for (int j = 0; j < 8; j++) {
        int L = (lane << 3) + j;               // leaves [32*lane+4j, +4)
        float4 t = buf[L ^ ((L >> 3) & 7)];
        s2[2*j]   = t.x + t.y;
        s2[2*j+1] = t.z + t.w;
    }

    // ---- within-lane sum tree ----
    float s4[8], s8[4], s16[2];
    #pragma unroll
    for (int i = 0; i < 8; i++) s4[i] = s2[2*i] + s2[2*i+1];
    #pragma unroll
    for (int i = 0; i < 4; i++) s8[i] = s4[2*i] + s4[2*i+1];
    s16[0] = s8[0] + s8[1];
    s16[1] = s8[2] + s8[3];
    float sum = s16[0] + s16[1];               // sum of my 32 leaves

    // ---- cross-lane levels d=4..0 (butterfly) ----
    // step s: group = 2^s lanes (32*2^s leaves); prob = sigmoid(my-sib mean diff)
    float acc = 1.0f;
    float inv = 1.0f / 32.0f;
    #pragma unroll
    for (int s = 0; s < 5; s++) {
        float part = __shfl_xor_sync(FULL_MASK, sum, 1 << s);
        acc *= fsigmoid((sum - part) * inv);
        sum += part;
        inv *= 0.5f;
    }

    // ---- within-lane top-down: levels d=5..8 ----
    float p16[2];
    {
        float pl = fsigmoid((s16[0] - s16[1]) * (1.0f / 16.0f));
        float a = acc * pl;  p16[0] = a;  p16[1] = acc - a;
    }
    float p8[4];
    #pragma unroll
    for (int i = 0; i < 2; i++) {
        float pl = fsigmoid((s8[2*i] - s8[2*i+1]) * 0.125f);
        float a = p16[i] * pl;  p8[2*i] = a;  p8[2*i+1] = p16[i] - a;
    }
    float p4[8];
    #pragma unroll
    for (int i = 0; i < 4; i++) {
        float pl = fsigmoid((s4[2*i] - s4[2*i+1]) * 0.25f);
        float a = p8[i] * pl;  p4[2*i] = a;  p4[2*i+1] = p8[i] - a;
    }
    float p2[16];
    #pragma unroll
    for (int i = 0; i < 8; i++) {
        float pl = fsigmoid((s2[2*i] - s2[2*i+1]) * 0.5f);
        float a = p4[i] * pl;  p2[2*i] = a;  p2[2*i+1] = p4[i] - a;
    }

    // ---- level d=9 fused into output: re-read input tile, write result ----
    // Each slot L = lane*8+j is read and written only by this lane here,
    // so no cross-lane sync is needed before this phase.
    #pragma unroll
    for (int j = 0; j < 8; j++) {
        int L = (lane << 3) + j;
        int S = L ^ ((L >> 3) & 7);
        float4 t = buf[S];
        float pl0 = fsigmoid(t.x - t.y);
        float a0 = p2[2*j] * pl0,   b0 = p2[2*j]   - a0;
        float pl1 = fsigmoid(t.z - t.w);
        float a1 = p2[2*j+1] * pl1, b1 = p2[2*j+1] - a1;
        buf[S] = make_float4(a0, b0, a1, b1);
    }
    __syncwarp();

    // ---- SMEM -> coalesced global store ----
    float4* rout = reinterpret_cast<float4*>(out) + (size_t)row * 256;
    #pragma unroll
    for (int k = 0; k < 8; k++) {
        int L = lane + (k << 5);
        rout[L] = buf[L ^ ((L >> 3) & 7)];
    }
}

extern "C" void kernel_launch(void* const* d_in, const int* in_sizes, int n_in,
                              void* d_out, int out_size)
{
    const float* in = (const float*)d_in[0];
    float* out = (float*)d_out;
    int rows = in_sizes[0] / 1024;             // BATCH = 16384
    nbdt_kernel<<<rows / 8, 256>>>(in, out);
}

// round 3
// speedup vs baseline: 1.2627x; 1.1073x over previous
#include <cuda_runtime.h>

#define FULL_MASK 0xffffffffu

// softmax over 2 children collapses to sigmoid of the mean difference
__device__ __forceinline__ float fsigmoid(float x) {
    return __fdividef(1.0f, 1.0f + __expf(-x));
}

// padded SMEM index: one extra float per 32 -> both transpose directions
// (write lane+32k / read 8t+j, and vice versa) are bank-conflict-free.
__device__ __forceinline__ int padidx(int L) { return L + (L >> 5); }

// One warp per row of 1024 floats, complete binary tree depth 10.
// Phase A (coalesced ownership, L = lane+32k): load float4s, compute
//   per-float4 sum s4 and the deep-level diffs (d8, d9a, d9b) in registers;
//   stage ONLY s4 (1KB) through padded SMEM to switch ownership.
// Phase B (contiguous ownership, lane t owns float4s 8t..8t+7): within-lane
//   sum tree (levels d=5..7) + cross-lane shfl butterfly (levels d=0..4),
//   top-down path probabilities down to float4 granularity -> p4[8];
//   stage p4 back through SMEM.
// Phase C (coalesced ownership): finish levels d=8,9 from the registered
//   diffs and store coalesced float4 results directly to global.
__global__ void __launch_bounds__(256, 4)
nbdt_kernel(const float* __restrict__ in, float* __restrict__ out)
{
    __shared__ float sm[8 * 264];          // 264 = 256 + pad, ~1KB per warp
    const int warp = threadIdx.x >> 5;
    const int lane = threadIdx.x & 31;
    const int row  = (blockIdx.x << 3) + warp;
    float* buf = sm + warp * 264;

    const float4* rin  = reinterpret_cast<const float4*>(in)  + (size_t)row * 256;
    float4*       rout = reinterpret_cast<float4*>(out)       + (size_t)row * 256;

    // ---- Phase A: coalesced loads, per-float4 partials ----
    float d8[8], d9a[8], d9b[8];
    #pragma unroll
    for (int k = 0; k < 8; k++) {
        float4 t = rin[lane + (k << 5)];
        float sxy = t.x + t.y, szw = t.z + t.w;
        d8[k]  = sxy - szw;                // feeds level d=8 (scale 1/2)
        d9a[k] = t.x - t.y;                // level d=9
        d9b[k] = t.z - t.w;
        buf[padidx(lane + (k << 5))] = sxy + szw;   // s4 of float4 L
    }
    __syncwarp();

    // ---- Phase B: lane t owns leaves [32t, 32t+32) via s4 of float4s 8t..8t+7
    float s4[8];
    #pragma unroll
    for (int j = 0; j < 8; j++)
        s4[j] = buf[padidx((lane << 3) + j)];

    float s8[4], s16[2];
    #pragma unroll
    for (int i = 0; i < 4; i++) s8[i] = s4[2*i] + s4[2*i+1];
    s16[0] = s8[0] + s8[1];
    s16[1] = s8[2] + s8[3];
    float sum = s16[0] + s16[1];           // sum of my 32 leaves

    // cross-lane levels d=4..0: prob = sigmoid((my_sum - sib_sum)/blk)
    float acc = 1.0f;
    float inv = 1.0f / 32.0f;
    #pragma unroll
    for (int s = 0; s < 5; s++) {
        float part = __shfl_xor_sync(FULL_MASK, sum, 1 << s);
        acc *= fsigmoid((sum - part) * inv);
        sum += part;
        inv *= 0.5f;
    }

    // within-lane top-down: d=5 (16-leaf children), d=6 (8), d=7 (4)
    float p16[2];
    {
        float pl = fsigmoid((s16[0] - s16[1]) * (1.0f / 16.0f));
        float a = acc * pl;  p16[0] = a;  p16[1] = acc - a;
    }
    float p8[4];
    #pragma unroll
    for (int i = 0; i < 2; i++) {
        float pl = fsigmoid((s8[2*i] - s8[2*i+1]) * 0.125f);
        float a = p16[i] * pl;  p8[2*i] = a;  p8[2*i+1] = p16[i] - a;
    }
    // p4[j]: path probability down to 4-leaf block (float4) j of this lane.
    // Same lane reads then writes the same padded slots -> no sync needed here.
    #pragma unroll
    for (int i = 0; i < 4; i++) {
        float pl = fsigmoid((s4[2*i] - s4[2*i+1]) * 0.25f);
        float a = p8[i] * pl;
        buf[padidx((lane << 3) + 2*i)]     = a;
        buf[padidx((lane << 3) + 2*i + 1)] = p8[i] - a;
    }
    __syncwarp();

    // ---- Phase C: coalesced ownership again; finish d=8,9 and store ----
    #pragma unroll
    for (int k = 0; k < 8; k++) {
        float p  = buf[padidx(lane + (k << 5))];
        float pl = fsigmoid(d8[k] * 0.5f);
        float hi = p * pl, lo = p - hi;
        float pa = fsigmoid(d9a[k]);
        float ox = hi * pa, oy = hi - ox;
        float pb = fsigmoid(d9b[k]);
        float oz = lo * pb, ow = lo - oz;
        rout[lane + (k << 5)] = make_float4(ox, oy, oz, ow);
    }
}

extern "C" void kernel_launch(void* const* d_in, const int* in_sizes, int n_in,
                              void* d_out, int out_size)
{
    const float* in = (const float*)d_in[0];
    float* out = (float*)d_out;
    int rows = in_sizes[0] / 1024;             // BATCH = 16384
    nbdt_kernel<<<rows / 8, 256>>>(in, out);
}

// round 8
// speedup vs baseline: 1.3464x; 1.0663x over previous
#include <cuda_runtime.h>

#define FULL_MASK 0xffffffffu

// softmax over 2 children collapses to sigmoid of the mean difference.
__device__ __forceinline__ float fsigmoid(float x) {
    return __fdividef(1.0f, 1.0f + __expf(-x));
}

// padded SMEM index for the s8 transpose: conflict-free both directions
__device__ __forceinline__ int padidx(int L) { return L + (L >> 5); }

// 256-bit global load, L2 evict_last (input stays resident across replays).
__device__ __forceinline__ void ldg256_evl(const float* p, float v[8]) {
    unsigned r0,r1,r2,r3,r4,r5,r6,r7;
    asm volatile("ld.global.nc.L2::evict_last.v8.b32 {%0,%1,%2,%3,%4,%5,%6,%7}, [%8];"
        : "=r"(r0),"=r"(r1),"=r"(r2),"=r"(r3),
          "=r"(r4),"=r"(r5),"=r"(r6),"=r"(r7) : "l"(p));
    v[0]=__uint_as_float(r0); v[1]=__uint_as_float(r1);
    v[2]=__uint_as_float(r2); v[3]=__uint_as_float(r3);
    v[4]=__uint_as_float(r4); v[5]=__uint_as_float(r5);
    v[6]=__uint_as_float(r6); v[7]=__uint_as_float(r7);
}
// 256-bit global store, L2 evict_first (output streams through L2).
__device__ __forceinline__ void stg256_evf(float* p, const float v[8]) {
    asm volatile("st.global.L2::evict_first.v8.b32 [%0], {%1,%2,%3,%4,%5,%6,%7,%8};"
        :: "l"(p),
           "r"(__float_as_uint(v[0])), "r"(__float_as_uint(v[1])),
           "r"(__float_as_uint(v[2])), "r"(__float_as_uint(v[3])),
           "r"(__float_as_uint(v[4])), "r"(__float_as_uint(v[5])),
           "r"(__float_as_uint(v[6])), "r"(__float_as_uint(v[7]))
        : "memory");
}

// One warp per row of 1024 floats, complete binary tree depth 10.
// Chunk M (0..127) = aligned 8-leaf block = a d=7 subtree.
// Phase A (coalesced, M = lane+32k, k<4): 256-bit load; compute in registers
//   the chunk sum s8, and diffs d7 (kept in regs), d8 (float2 -> SMEM),
//   d9 (float4 -> SMEM). Only s8 (0.5KB/row) crosses the ownership transpose.
// Phase B (lane t owns chunks 4t..4t+3 = leaves [32t,32t+32)): within-lane
//   sum tree (d=5,6) + 5-step shfl butterfly (d=0..4); top-down path probs
//   to chunk granularity p8, staged back through the padded slots.
// Phase C (coalesced): finish d=7,8,9 from the staged diffs, 256-bit store.
__global__ void __launch_bounds__(256, 5)
nbdt_kernel(const float* __restrict__ in, float* __restrict__ out)
{
    __shared__ float  s8s[8][132];     // s8 / p8 transpose (128 + pad)
    __shared__ float4 d9s[8][128];     // leaf-pair diffs (SMEM reg-spill)
    __shared__ float2 d8s[8][128];     // 2-leaf-block diffs (SMEM reg-spill)
    const int warp = threadIdx.x >> 5;
    const int lane = threadIdx.x & 31;
    const int row  = (blockIdx.x << 3) + warp;

    const float* rin  = in  + (size_t)row * 1024;
    float*       rout = out + (size_t)row * 1024;

    // ---- Phase A ----
    float d7[4];
    #pragma unroll
    for (int k = 0; k < 4; k++) {
        int M = lane + (k << 5);
        float v[8];
        ldg256_evl(rin + (M << 3), v);
        float a0 = v[0]+v[1], a1 = v[2]+v[3], a2 = v[4]+v[5], a3 = v[6]+v[7];
        d9s[warp][M] = make_float4(v[0]-v[1], v[2]-v[3], v[4]-v[5], v[6]-v[7]);
        float b0 = a0 + a1, b1 = a2 + a3;
        d8s[warp][M] = make_float2(a0 - a1, a2 - a3);
        d7[k] = b0 - b1;
        s8s[warp][padidx(M)] = b0 + b1;
    }
    __syncwarp();

    // ---- Phase B ----
    float s8[4];
    #pragma unroll
    for (int j = 0; j < 4; j++)
        s8[j] = s8s[warp][padidx((lane << 2) + j)];
    float s16[2] = { s8[0] + s8[1], s8[2] + s8[3] };
    float sum = s16[0] + s16[1];           // sum of my 32 leaves

    // cross-lane levels d=4..0: prob = sigmoid((my_sum - sib_sum)/blk)
    float acc = 1.0f;
    float inv = 1.0f / 32.0f;
    #pragma unroll
    for (int s = 0; s < 5; s++) {
        float part = __shfl_xor_sync(FULL_MASK, sum, 1 << s);
        acc *= fsigmoid((sum - part) * inv);
        sum += part;
        inv *= 0.5f;
    }

    // d=5 (children of 16 leaves)
    float p16[2];
    {
        float pl = fsigmoid((s16[0] - s16[1]) * (1.0f / 16.0f));
        float a = acc * pl;  p16[0] = a;  p16[1] = acc - a;
    }
    // d=6 (children of 8) -> per-chunk path prob p8, staged back.
    // Same-lane slots: no cross-lane sync needed before the writes.
    #pragma unroll
    for (int i = 0; i < 2; i++) {
        float pl = fsigmoid((s8[2*i] - s8[2*i+1]) * 0.125f);
        float a = p16[i] * pl;
        s8s[warp][padidx((lane << 2) + 2*i)]     = a;
        s8s[warp][padidx((lane << 2) + 2*i + 1)] = p16[i] - a;
    }
    __syncwarp();

    // ---- Phase C ----
    #pragma unroll
    for (int k = 0; k < 4; k++) {
        int M = lane + (k << 5);
        float p   = s8s[warp][padidx(M)];
        float pl7 = fsigmoid(d7[k] * 0.25f);
        float hi = p * pl7, lo = p - hi;
        float2 d8 = d8s[warp][M];
        float pa = fsigmoid(d8.x * 0.5f);
        float q0 = hi * pa, q1 = hi - q0;
        float pb = fsigmoid(d8.y * 0.5f);
        float q2 = lo * pb, q3 = lo - q2;
        float4 d9 = d9s[warp][M];
        float v[8];
        float t0 = fsigmoid(d9.x); v[0] = q0 * t0; v[1] = q0 - v[0];
        float t1 = fsigmoid(d9.y); v[2] = q1 * t1; v[3] = q1 - v[2];
        float t2 = fsigmoid(d9.z); v[4] = q2 * t2; v[5] = q2 - v[4];
        float t3 = fsigmoid(d9.w); v[6] = q3 * t3; v[7] = q3 - v[6];
        stg256_evf(rout + (M << 3), v);
    }
}

extern "C" void kernel_launch(void* const* d_in, const int* in_sizes, int n_in,
                              void* d_out, int out_size)
{
    const float* in = (const float*)d_in[0];
    float* out = (float*)d_out;
    int rows = in_sizes[0] / 1024;             // BATCH = 16384
    nbdt_kernel<<<rows / 8, 256>>>(in, out);
}